// round 9
// baseline (speedup 1.0000x reference)
#include <cuda_runtime.h>

#define NN 16384
#define CAP 96

// Scratch (no allocations). Referenced ONLY from device code.
__device__ int   g_cnt[NN];
__device__ int   g_nbr[NN * CAP];
__device__ float g_z0[NN * 128];
__device__ float g_r0[NN * 128];
__device__ float g_z1[NN * 128];
__device__ float g_r1[NN * 128];
__device__ float g_z2[NN * 64];
__device__ float g_r2[NN * 64];
__device__ float g_h[NN * 128];

__device__ __forceinline__ float* zbuf(int s) { return s == 0 ? g_z0 : (s == 1 ? g_z1 : g_z2); }
__device__ __forceinline__ float* rbuf(int s) { return s == 0 ? g_r0 : (s == 1 ? g_r1 : g_r2); }

__global__ void zero_cnt_kernel() {
    int i = blockIdx.x * blockDim.x + threadIdx.x;
    if (i < NN) g_cnt[i] = 0;
}

// ---------------------------------------------------------------------------
// Low-register GEMM block (used inside fused kernels, hidden under adj scan):
// 128x64 tile of A[N,128] @ Bv[2*fout,128]^T, fout=128. BK=32, 256 thr, 8x4.
// ---------------------------------------------------------------------------
__device__ __forceinline__ void gemm_block64(
    const float* __restrict__ A,
    const float* __restrict__ Wl, const float* __restrict__ Wr,
    const float* __restrict__ bias, int zsel, int rb, int cb,
    float (*As)[128], float (*Bs)[64])
{
    const int fout = 128;
    int tid = threadIdx.x;
    int rowBase = rb * 128;
    int vcol = cb * 64;

    const float* B;
    float* out;
    int colBase;
    bool addb;
    if (vcol < fout) { B = Wl; out = zbuf(zsel); colBase = vcol;        addb = false; }
    else             { B = Wr; out = rbuf(zsel); colBase = vcol - fout; addb = true;  }

    int tx = tid & 15;
    int ty = tid >> 4;

    float acc[8][4];
#pragma unroll
    for (int i = 0; i < 8; i++)
#pragma unroll
        for (int j = 0; j < 4; j++) acc[i][j] = 0.0f;

#pragma unroll 1
    for (int kt = 0; kt < 4; kt++) {
        int koff = kt * 32;
#pragma unroll
        for (int i = 0; i < 4; i++) {
            int lin = tid + i * 256;
            int m = lin >> 3;
            int kq = lin & 7;
            float4 v = *reinterpret_cast<const float4*>(
                &A[(size_t)(rowBase + m) * 128 + koff + kq * 4]);
            As[kq * 4 + 0][m] = v.x;
            As[kq * 4 + 1][m] = v.y;
            As[kq * 4 + 2][m] = v.z;
            As[kq * 4 + 3][m] = v.w;
        }
#pragma unroll
        for (int i = 0; i < 2; i++) {
            int lin = tid + i * 256;
            int o = lin >> 3;
            int kq = lin & 7;
            float4 v = *reinterpret_cast<const float4*>(
                &B[(size_t)(colBase + o) * 128 + koff + kq * 4]);
            Bs[kq * 4 + 0][o] = v.x;
            Bs[kq * 4 + 1][o] = v.y;
            Bs[kq * 4 + 2][o] = v.z;
            Bs[kq * 4 + 3][o] = v.w;
        }
        __syncthreads();

#pragma unroll
        for (int kk = 0; kk < 32; kk++) {
            float4 a0 = *reinterpret_cast<float4*>(&As[kk][ty * 8]);
            float4 a1 = *reinterpret_cast<float4*>(&As[kk][ty * 8 + 4]);
            float4 b0 = *reinterpret_cast<float4*>(&Bs[kk][tx * 4]);
            float am[8] = {a0.x, a0.y, a0.z, a0.w, a1.x, a1.y, a1.z, a1.w};
            float bn[4] = {b0.x, b0.y, b0.z, b0.w};
#pragma unroll
            for (int i = 0; i < 8; i++)
#pragma unroll
                for (int j = 0; j < 4; j++)
                    acc[i][j] = fmaf(am[i], bn[j], acc[i][j]);
        }
        __syncthreads();
    }

#pragma unroll
    for (int i = 0; i < 8; i++) {
        int m = rowBase + ty * 8 + i;
#pragma unroll
        for (int j = 0; j < 4; j++) {
            int o = colBase + tx * 4 + j;
            float v = acc[i][j];
            if (addb) v += bias[o];
            out[(size_t)m * fout + o] = v;
        }
    }
}

__device__ __forceinline__ float4 f4add(float4 a, float4 b) {
    return make_float4(a.x + b.x, a.y + b.y, a.z + b.z, a.w + b.w);
}

// ---------------------------------------------------------------------------
// Gather block (F=128, 256 threads, 8 targets/block):
// h[t] = relu( mean_{n in nbr(t)} z[n] + r[t] )
// ---------------------------------------------------------------------------
__device__ __forceinline__ void gather128_block(int zsel, int t0) {
    int t = t0 + (threadIdx.x >> 5);
    int c = threadIdx.x & 31;            // float4 column (32 * 4 = 128 feats)

    int deg = min(g_cnt[t], CAP);
    const int* nb = &g_nbr[t * CAP];
    const float4* z4 = reinterpret_cast<const float4*>(zbuf(zsel));

    float4 s = make_float4(0.f, 0.f, 0.f, 0.f);
    int i = 0;
    for (; i + 4 <= deg; i += 4) {
        int4 nn = *reinterpret_cast<const int4*>(&nb[i]);
        float4 a = z4[(size_t)nn.x * 32 + c];
        float4 b = z4[(size_t)nn.y * 32 + c];
        float4 cc = z4[(size_t)nn.z * 32 + c];
        float4 d = z4[(size_t)nn.w * 32 + c];
        s = f4add(s, f4add(f4add(a, b), f4add(cc, d)));
    }
    for (; i < deg; i++)
        s = f4add(s, z4[(size_t)nb[i] * 32 + c]);

    float dinv = (deg > 0) ? (1.0f / (float)deg) : 0.0f;
    float4 rr = reinterpret_cast<const float4*>(rbuf(zsel))[(size_t)t * 32 + c];
    float4 o;
    o.x = fmaxf(s.x * dinv + rr.x, 0.f);
    o.y = fmaxf(s.y * dinv + rr.y, 0.f);
    o.z = fmaxf(s.z * dinv + rr.z, 0.f);
    o.w = fmaxf(s.w * dinv + rr.w, 0.f);
    reinterpret_cast<float4*>(g_h)[(size_t)t * 32 + c] = o;
}

// ---------------------------------------------------------------------------
// Fused phase kernel. Block partition: [gemm | gather | scan-col-stripe].
// gemm: low-reg 128x64 tiles of A@[Wl|Wr]^T (fout=128) into z/r[zsel_gemm].
// gather: layer-0 style gather of 8 targets per block (reads z/r[gath_zsel]).
// scan: column stripe q (cols [q*4096,(q+1)*4096)) of the 1 GB dense adj.
// ---------------------------------------------------------------------------
__global__ void __launch_bounds__(256) fused_phase_kernel(
    const float* __restrict__ Aext, const float* __restrict__ adj,
    const float* __restrict__ Wl, const float* __restrict__ Wr,
    const float* __restrict__ bias,
    int asel,            // 0: A = Aext (x), 1: A = g_h
    int zsel_gemm,       // output buffer set for gemm
    int gemm_rowbase, int gemm_blocks,
    int gath_tbase, int gath_blocks, int gath_zsel,
    int scan_q)
{
    __shared__ float As[32][128];
    __shared__ float Bs[32][64];

    int bid = blockIdx.x;
    if (bid < gemm_blocks) {
        const float* A = asel == 0 ? Aext : g_h;
        gemm_block64(A, Wl, Wr, bias, zsel_gemm,
                     (gemm_rowbase >> 7) + (bid >> 2), bid & 3, As, Bs);
        return;
    }
    bid -= gemm_blocks;
    if (bid < gath_blocks) {
        gather128_block(gath_zsel, gath_tbase + bid * 8);
        return;
    }
    bid -= gath_blocks;

    // Scan stripe q: per thread 8 float4 (128 B), coalesced.
    const float4* adj4 = reinterpret_cast<const float4*>(adj);
    size_t base = (size_t)bid * 2048 + threadIdx.x;
    int qoff = scan_q * 1024;

    float4 v[8];
#pragma unroll
    for (int i = 0; i < 8; i++) {
        size_t s = base + (size_t)i * 256;
        int r = (int)(s >> 10);
        int j = (int)(s & 1023);
        v[i] = __ldcs(&adj4[(size_t)r * 4096 + qoff + j]);
    }

#pragma unroll
    for (int i = 0; i < 8; i++) {
        size_t s = base + (size_t)i * 256;
        int r = (int)(s >> 10);
        int c0 = (qoff + (int)(s & 1023)) << 2;
        if (v[i].x != 0.0f) { int p = atomicAdd(&g_cnt[c0 + 0], 1); if (p < CAP) g_nbr[(c0 + 0) * CAP + p] = r; }
        if (v[i].y != 0.0f) { int p = atomicAdd(&g_cnt[c0 + 1], 1); if (p < CAP) g_nbr[(c0 + 1) * CAP + p] = r; }
        if (v[i].z != 0.0f) { int p = atomicAdd(&g_cnt[c0 + 2], 1); if (p < CAP) g_nbr[(c0 + 2) * CAP + p] = r; }
        if (v[i].w != 0.0f) { int p = atomicAdd(&g_cnt[c0 + 3], 1); if (p < CAP) g_nbr[(c0 + 3) * CAP + p] = r; }
    }
}

// ---------------------------------------------------------------------------
// Fast double-buffered SGEMM (standalone tail): 128x128 tile, BK=8, 8x8.
// A = g_h. Virtual B rows: o < fout -> Wl (-> z[zsel]), else Wr (-> r[zsel], +b).
// ---------------------------------------------------------------------------
#define SPAD 132

__global__ void __launch_bounds__(256, 2) fast_gemm_kernel(
    const float* __restrict__ Wl, const float* __restrict__ Wr,
    const float* __restrict__ bias, int fout, int rowbase0, int zsel)
{
    __shared__ float As[2][8][SPAD];
    __shared__ float Bs[2][8][SPAD];
    const float* A = g_h;

    int tid = threadIdx.x;
    int rowBase = rowbase0 + blockIdx.x * 128;
    int cbase = blockIdx.y * 128;

    int tx = tid & 15;
    int ty = tid >> 4;

    int lm = tid >> 1;
    int lkq = tid & 1;
    const float* aRow = &A[(size_t)(rowBase + lm) * 128 + lkq * 4];
    int ov = cbase + lm;
    const float* bRow = (ov < fout) ? &Wl[(size_t)ov * 128 + lkq * 4]
                                    : &Wr[(size_t)(ov - fout) * 128 + lkq * 4];

    float acc[8][8];
#pragma unroll
    for (int i = 0; i < 8; i++)
#pragma unroll
        for (int j = 0; j < 8; j++) acc[i][j] = 0.0f;

    float4 pa = *reinterpret_cast<const float4*>(aRow);
    float4 pb = *reinterpret_cast<const float4*>(bRow);
    As[0][lkq * 4 + 0][lm] = pa.x; As[0][lkq * 4 + 1][lm] = pa.y;
    As[0][lkq * 4 + 2][lm] = pa.z; As[0][lkq * 4 + 3][lm] = pa.w;
    Bs[0][lkq * 4 + 0][lm] = pb.x; Bs[0][lkq * 4 + 1][lm] = pb.y;
    Bs[0][lkq * 4 + 2][lm] = pb.z; Bs[0][lkq * 4 + 3][lm] = pb.w;
    __syncthreads();

#pragma unroll 1
    for (int kt = 0; kt < 16; kt++) {
        int buf = kt & 1;
        if (kt < 15) {
            pa = *reinterpret_cast<const float4*>(aRow + (kt + 1) * 8);
            pb = *reinterpret_cast<const float4*>(bRow + (kt + 1) * 8);
        }
#pragma unroll
        for (int kk = 0; kk < 8; kk++) {
            float4 a0 = *reinterpret_cast<float4*>(&As[buf][kk][ty * 4]);
            float4 a1 = *reinterpret_cast<float4*>(&As[buf][kk][64 + ty * 4]);
            float4 b0 = *reinterpret_cast<float4*>(&Bs[buf][kk][tx * 4]);
            float4 b1 = *reinterpret_cast<float4*>(&Bs[buf][kk][64 + tx * 4]);
            float am[8] = {a0.x, a0.y, a0.z, a0.w, a1.x, a1.y, a1.z, a1.w};
            float bn[8] = {b0.x, b0.y, b0.z, b0.w, b1.x, b1.y, b1.z, b1.w};
#pragma unroll
            for (int i = 0; i < 8; i++)
#pragma unroll
                for (int j = 0; j < 8; j++)
                    acc[i][j] = fmaf(am[i], bn[j], acc[i][j]);
        }
        if (kt < 15) {
            __syncthreads();
            int nb = buf ^ 1;
            As[nb][lkq * 4 + 0][lm] = pa.x; As[nb][lkq * 4 + 1][lm] = pa.y;
            As[nb][lkq * 4 + 2][lm] = pa.z; As[nb][lkq * 4 + 3][lm] = pa.w;
            Bs[nb][lkq * 4 + 0][lm] = pb.x; Bs[nb][lkq * 4 + 1][lm] = pb.y;
            Bs[nb][lkq * 4 + 2][lm] = pb.z; Bs[nb][lkq * 4 + 3][lm] = pb.w;
            __syncthreads();
        }
    }

#pragma unroll
    for (int g = 0; g < 2; g++) {
        int ovc = cbase + g * 64 + tx * 4;
        bool isR = (ovc >= fout);
        int col = isR ? (ovc - fout) : ovc;
        float* dst = isR ? rbuf(zsel) : zbuf(zsel);
        float4 bv = make_float4(0.f, 0.f, 0.f, 0.f);
        if (isR) bv = *reinterpret_cast<const float4*>(&bias[col]);
#pragma unroll
        for (int h = 0; h < 2; h++) {
#pragma unroll
            for (int i = 0; i < 4; i++) {
                int m = rowBase + h * 64 + ty * 4 + i;
                float4 o;
                o.x = acc[h * 4 + i][g * 4 + 0] + bv.x;
                o.y = acc[h * 4 + i][g * 4 + 1] + bv.y;
                o.z = acc[h * 4 + i][g * 4 + 2] + bv.z;
                o.w = acc[h * 4 + i][g * 4 + 3] + bv.w;
                *reinterpret_cast<float4*>(&dst[(size_t)m * fout + col]) = o;
            }
        }
    }
}

// Final gather (F=64, no relu): out[t] = mean(z2[nbr]) + r2[t]
__global__ void gather64_kernel(float* __restrict__ out) {
    int t = blockIdx.x * 16 + (threadIdx.x >> 4);
    int c = threadIdx.x & 15;

    int deg = min(g_cnt[t], CAP);
    const int* nb = &g_nbr[t * CAP];
    const float4* z4 = reinterpret_cast<const float4*>(g_z2);

    float4 s = make_float4(0.f, 0.f, 0.f, 0.f);
    int i = 0;
    for (; i + 4 <= deg; i += 4) {
        int4 nn = *reinterpret_cast<const int4*>(&nb[i]);
        float4 a = z4[(size_t)nn.x * 16 + c];
        float4 b = z4[(size_t)nn.y * 16 + c];
        float4 cc = z4[(size_t)nn.z * 16 + c];
        float4 d = z4[(size_t)nn.w * 16 + c];
        s = f4add(s, f4add(f4add(a, b), f4add(cc, d)));
    }
    for (; i < deg; i++)
        s = f4add(s, z4[(size_t)nb[i] * 16 + c]);

    float dinv = (deg > 0) ? (1.0f / (float)deg) : 0.0f;
    float4 rr = reinterpret_cast<const float4*>(g_r2)[(size_t)t * 16 + c];
    float4 o;
    o.x = s.x * dinv + rr.x;
    o.y = s.y * dinv + rr.y;
    o.z = s.z * dinv + rr.z;
    o.w = s.w * dinv + rr.w;
    reinterpret_cast<float4*>(out)[(size_t)t * 16 + c] = o;
}

extern "C" void kernel_launch(void* const* d_in, const int* in_sizes, int n_in,
                              void* d_out, int out_size) {
    const float* x   = (const float*)d_in[0];
    const float* adj = (const float*)d_in[1];
    const float* Wl0 = (const float*)d_in[2];
    const float* b0  = (const float*)d_in[3];
    const float* Wr0 = (const float*)d_in[4];
    const float* Wl1 = (const float*)d_in[5];
    const float* b1  = (const float*)d_in[6];
    const float* Wr1 = (const float*)d_in[7];
    const float* Wl2 = (const float*)d_in[8];
    const float* b2  = (const float*)d_in[9];
    const float* Wr2 = (const float*)d_in[10];
    float* out = (float*)d_out;

    const int SCAN_B = 8192;   // blocks per quarter-column-stripe

    zero_cnt_kernel<<<NN / 256, 256>>>();

    // K2: layer-0 transform (x -> z0,r0; 512 blocks) + scan stripe Q0
    fused_phase_kernel<<<512 + SCAN_B, 256>>>(
        x, adj, Wl0, Wr0, b0, /*asel*/0, /*zsel_gemm*/0,
        /*gemm_rowbase*/0, /*gemm_blocks*/512,
        /*gath_tbase*/0, /*gath_blocks*/0, /*gath_zsel*/0, /*scan_q*/0);

    // K3: scan Q1 + gather0 targets [0, 4096)
    fused_phase_kernel<<<512 + SCAN_B, 256>>>(
        x, adj, Wl1, Wr1, b1, 1, 1, 0, 0,
        0, 512, 0, 1);

    // K4: scan Q2 + gather0 [4096, 8192) + gemm1 rows [0, 4096)
    fused_phase_kernel<<<128 + 512 + SCAN_B, 256>>>(
        x, adj, Wl1, Wr1, b1, 1, 1, 0, 128,
        4096, 512, 0, 2);

    // K5: scan Q3 + gather0 [8192, 12288) + gemm1 rows [4096, 8192)
    fused_phase_kernel<<<128 + 512 + SCAN_B, 256>>>(
        x, adj, Wl1, Wr1, b1, 1, 1, 4096, 128,
        8192, 512, 0, 3);

    // K6: gather0 [12288, 16384) + gemm1 rows [8192, 12288)  (no scan)
    fused_phase_kernel<<<128 + 512, 256>>>(
        x, adj, Wl1, Wr1, b1, 1, 1, 8192, 128,
        12288, 512, 0, 0);

    // K7: gemm1 remainder rows [12288, 16384) — fast gemm
    fast_gemm_kernel<<<dim3(32, 2), 256>>>(Wl1, Wr1, b1, 128, 12288, 1);

    // K8: gather1 full (reads z1/r1, writes g_h)
    fused_phase_kernel<<<2048, 256>>>(
        x, adj, Wl1, Wr1, b1, 1, 1, 0, 0,
        0, 2048, 1, 0);

    // K9: gemm2 (fout=64, virtual cols=128) -> z2/r2
    fast_gemm_kernel<<<dim3(128, 1), 256>>>(Wl2, Wr2, b2, 64, 0, 2);

    // K10: final gather -> d_out (no relu)
    gather64_kernel<<<NN / 16, 256>>>(out);
}

// round 11
// speedup vs baseline: 1.2790x; 1.2790x over previous
#include <cuda_runtime.h>

#define NN 16384
#define CAP 96
#define GEMM0_BLOCKS 1024
#define BUILD_BLOCKS 32768

// Scratch (no allocations). Referenced ONLY from device code.
__device__ int   g_cnt[NN];
__device__ int   g_nbr[NN * CAP];
__device__ float g_z[NN * 128];
__device__ float g_r[NN * 128];
__device__ float g_h[NN * 128];

__global__ void zero_cnt_kernel() {
    int i = blockIdx.x * blockDim.x + threadIdx.x;
    if (i < NN) g_cnt[i] = 0;
}

// ---------------------------------------------------------------------------
// LOW-REG GEMM block (layer 0 only, hidden under adj scan):
// 64x64 tile of A[N,128] @ Bv[256,128]^T (fout=128). BK=32, 256 thr, TM=4xTN=4.
// Kept small on purpose: ~42 regs so the fused kernel's SCAN blocks get
// high occupancy (the scan is the critical path; this gemm is hidden).
// ---------------------------------------------------------------------------
__device__ __forceinline__ void gemm_block_small(
    const float* __restrict__ A,
    const float* __restrict__ Wl, const float* __restrict__ Wr,
    const float* __restrict__ bias, int rb, int cb,
    float (*As)[64], float (*Bs)[64])
{
    const int fout = 128;
    int tid = threadIdx.x;
    int rowBase = rb * 64;
    int vcol = cb * 64;

    const float* B;
    float* out;
    int colBase;
    bool addb;
    if (vcol < fout) { B = Wl; out = g_z; colBase = vcol;        addb = false; }
    else             { B = Wr; out = g_r; colBase = vcol - fout; addb = true;  }

    int tx = tid & 15;    // col (4 each)
    int ty = tid >> 4;    // row (4 each)

    float acc[4][4];
#pragma unroll
    for (int i = 0; i < 4; i++)
#pragma unroll
        for (int j = 0; j < 4; j++) acc[i][j] = 0.0f;

#pragma unroll 1
    for (int kt = 0; kt < 4; kt++) {
        int koff = kt * 32;
        // As: 64 rows x 32 cols = 512 float4 -> 2 per thread
#pragma unroll
        for (int i = 0; i < 2; i++) {
            int lin = tid + i * 256;
            int m = lin >> 3;
            int kq = lin & 7;
            float4 v = *reinterpret_cast<const float4*>(
                &A[(size_t)(rowBase + m) * 128 + koff + kq * 4]);
            As[kq * 4 + 0][m] = v.x;
            As[kq * 4 + 1][m] = v.y;
            As[kq * 4 + 2][m] = v.z;
            As[kq * 4 + 3][m] = v.w;
        }
        // Bs: 64 rows x 32 cols = 512 float4 -> 2 per thread
#pragma unroll
        for (int i = 0; i < 2; i++) {
            int lin = tid + i * 256;
            int o = lin >> 3;
            int kq = lin & 7;
            float4 v = *reinterpret_cast<const float4*>(
                &B[(size_t)(colBase + o) * 128 + koff + kq * 4]);
            Bs[kq * 4 + 0][o] = v.x;
            Bs[kq * 4 + 1][o] = v.y;
            Bs[kq * 4 + 2][o] = v.z;
            Bs[kq * 4 + 3][o] = v.w;
        }
        __syncthreads();

#pragma unroll
        for (int kk = 0; kk < 32; kk++) {
            float4 a0 = *reinterpret_cast<float4*>(&As[kk][ty * 4]);
            float4 b0 = *reinterpret_cast<float4*>(&Bs[kk][tx * 4]);
            float am[4] = {a0.x, a0.y, a0.z, a0.w};
            float bn[4] = {b0.x, b0.y, b0.z, b0.w};
#pragma unroll
            for (int i = 0; i < 4; i++)
#pragma unroll
                for (int j = 0; j < 4; j++)
                    acc[i][j] = fmaf(am[i], bn[j], acc[i][j]);
        }
        __syncthreads();
    }

#pragma unroll
    for (int i = 0; i < 4; i++) {
        int m = rowBase + ty * 4 + i;
        int o = colBase + tx * 4;
        float4 v;
        v.x = acc[i][0]; v.y = acc[i][1]; v.z = acc[i][2]; v.w = acc[i][3];
        if (addb) {
            float4 bv = *reinterpret_cast<const float4*>(&bias[o]);
            v.x += bv.x; v.y += bv.y; v.z += bv.z; v.w += bv.w;
        }
        *reinterpret_cast<float4*>(&out[(size_t)m * fout + o]) = v;
    }
}

// ---------------------------------------------------------------------------
// Fused kernel: blocks [0, GEMM0_BLOCKS) = layer-0 transform (x -> g_z, g_r)
// via the small gemm; the rest scan 1 GB adj (whole rows) and build lists.
// Lean reg budget -> scan blocks keep ~5 CTAs/SM.
// ---------------------------------------------------------------------------
__global__ void __launch_bounds__(256) fused_gemm0_build_kernel(
    const float* __restrict__ x, const float* __restrict__ adj,
    const float* __restrict__ Wl0, const float* __restrict__ Wr0,
    const float* __restrict__ b0)
{
    __shared__ float As[32][64];
    __shared__ float Bs[32][64];

    int bid = blockIdx.x;
    if (bid < GEMM0_BLOCKS) {
        gemm_block_small(x, Wl0, Wr0, b0, bid >> 2, bid & 3, As, Bs);
        return;
    }

    // Build: each thread reads 8 float4 (128 B), coalesced per iteration.
    int bb = bid - GEMM0_BLOCKS;
    const float4* adj4 = reinterpret_cast<const float4*>(adj);
    size_t base = (size_t)bb * 2048 + threadIdx.x;

    float4 v[8];
#pragma unroll
    for (int i = 0; i < 8; i++) v[i] = __ldcs(&adj4[base + (size_t)i * 256]);

#pragma unroll
    for (int i = 0; i < 8; i++) {
        size_t idx = base + (size_t)i * 256;
        int r  = (int)(idx >> 12);          // 4096 float4 per adj row
        int c0 = (int)((idx & 4095) << 2);
        if (v[i].x != 0.0f) { int s = atomicAdd(&g_cnt[c0 + 0], 1); if (s < CAP) g_nbr[(c0 + 0) * CAP + s] = r; }
        if (v[i].y != 0.0f) { int s = atomicAdd(&g_cnt[c0 + 1], 1); if (s < CAP) g_nbr[(c0 + 1) * CAP + s] = r; }
        if (v[i].z != 0.0f) { int s = atomicAdd(&g_cnt[c0 + 2], 1); if (s < CAP) g_nbr[(c0 + 2) * CAP + s] = r; }
        if (v[i].w != 0.0f) { int s = atomicAdd(&g_cnt[c0 + 3], 1); if (s < CAP) g_nbr[(c0 + 3) * CAP + s] = r; }
    }
}

// ---------------------------------------------------------------------------
// Double-buffered SGEMM (layers 1 & 2): 128x128 tile, BK=8, TM=8 x TN=8.
// ---------------------------------------------------------------------------
#define SPAD 132

__global__ void __launch_bounds__(256, 2) gemm_kernel(
    const float* __restrict__ Wl, const float* __restrict__ Wr,
    const float* __restrict__ bias, int fout)
{
    __shared__ float As[2][8][SPAD];
    __shared__ float Bs[2][8][SPAD];
    const float* A = g_h;

    int tid = threadIdx.x;
    int rowBase = blockIdx.x * 128;
    int cbase = blockIdx.y * 128;

    int tx = tid & 15;
    int ty = tid >> 4;

    int lm = tid >> 1;
    int lkq = tid & 1;
    const float* aRow = &A[(size_t)(rowBase + lm) * 128 + lkq * 4];
    int ov = cbase + lm;
    const float* bRow = (ov < fout) ? &Wl[(size_t)ov * 128 + lkq * 4]
                                    : &Wr[(size_t)(ov - fout) * 128 + lkq * 4];

    float acc[8][8];
#pragma unroll
    for (int i = 0; i < 8; i++)
#pragma unroll
        for (int j = 0; j < 8; j++) acc[i][j] = 0.0f;

    float4 pa = *reinterpret_cast<const float4*>(aRow);
    float4 pb = *reinterpret_cast<const float4*>(bRow);
    As[0][lkq * 4 + 0][lm] = pa.x; As[0][lkq * 4 + 1][lm] = pa.y;
    As[0][lkq * 4 + 2][lm] = pa.z; As[0][lkq * 4 + 3][lm] = pa.w;
    Bs[0][lkq * 4 + 0][lm] = pb.x; Bs[0][lkq * 4 + 1][lm] = pb.y;
    Bs[0][lkq * 4 + 2][lm] = pb.z; Bs[0][lkq * 4 + 3][lm] = pb.w;
    __syncthreads();

#pragma unroll 1
    for (int kt = 0; kt < 16; kt++) {
        int buf = kt & 1;
        if (kt < 15) {
            pa = *reinterpret_cast<const float4*>(aRow + (kt + 1) * 8);
            pb = *reinterpret_cast<const float4*>(bRow + (kt + 1) * 8);
        }
#pragma unroll
        for (int kk = 0; kk < 8; kk++) {
            float4 a0 = *reinterpret_cast<float4*>(&As[buf][kk][ty * 4]);
            float4 a1 = *reinterpret_cast<float4*>(&As[buf][kk][64 + ty * 4]);
            float4 b0 = *reinterpret_cast<float4*>(&Bs[buf][kk][tx * 4]);
            float4 b1 = *reinterpret_cast<float4*>(&Bs[buf][kk][64 + tx * 4]);
            float am[8] = {a0.x, a0.y, a0.z, a0.w, a1.x, a1.y, a1.z, a1.w};
            float bn[8] = {b0.x, b0.y, b0.z, b0.w, b1.x, b1.y, b1.z, b1.w};
#pragma unroll
            for (int i = 0; i < 8; i++)
#pragma unroll
                for (int j = 0; j < 8; j++)
                    acc[i][j] = fmaf(am[i], bn[j], acc[i][j]);
        }
        if (kt < 15) {
            __syncthreads();
            int nb = buf ^ 1;
            As[nb][lkq * 4 + 0][lm] = pa.x; As[nb][lkq * 4 + 1][lm] = pa.y;
            As[nb][lkq * 4 + 2][lm] = pa.z; As[nb][lkq * 4 + 3][lm] = pa.w;
            Bs[nb][lkq * 4 + 0][lm] = pb.x; Bs[nb][lkq * 4 + 1][lm] = pb.y;
            Bs[nb][lkq * 4 + 2][lm] = pb.z; Bs[nb][lkq * 4 + 3][lm] = pb.w;
            __syncthreads();
        }
    }

#pragma unroll
    for (int g = 0; g < 2; g++) {
        int ovc = cbase + g * 64 + tx * 4;
        bool isR = (ovc >= fout);
        int col = isR ? (ovc - fout) : ovc;
        float* dst = isR ? g_r : g_z;
        float4 bv = make_float4(0.f, 0.f, 0.f, 0.f);
        if (isR) bv = *reinterpret_cast<const float4*>(&bias[col]);
#pragma unroll
        for (int h = 0; h < 2; h++) {
#pragma unroll
            for (int i = 0; i < 4; i++) {
                int m = rowBase + h * 64 + ty * 4 + i;
                float4 o;
                o.x = acc[h * 4 + i][g * 4 + 0] + bv.x;
                o.y = acc[h * 4 + i][g * 4 + 1] + bv.y;
                o.z = acc[h * 4 + i][g * 4 + 2] + bv.z;
                o.w = acc[h * 4 + i][g * 4 + 3] + bv.w;
                *reinterpret_cast<float4*>(&dst[(size_t)m * fout + col]) = o;
            }
        }
    }
}

__device__ __forceinline__ float4 f4add(float4 a, float4 b) {
    return make_float4(a.x + b.x, a.y + b.y, a.z + b.z, a.w + b.w);
}

// ---------------------------------------------------------------------------
// Gather: h[t] = act( deginv[t] * sum_{n in nbr(t)} z[n]  +  r[t] )
// ---------------------------------------------------------------------------
template <int F, bool RELU>
__global__ void gather_kernel(float* __restrict__ out_ext, int sel_out) {
    constexpr int TPT = F / 4;
    constexpr int TGT_PER_BLK = 128 / TPT;

    float* out = (sel_out == 0) ? out_ext : g_h;
    int lin = threadIdx.x;
    int t = blockIdx.x * TGT_PER_BLK + lin / TPT;
    int c = lin % TPT;

    int deg = min(g_cnt[t], CAP);
    const int* nb = &g_nbr[t * CAP];
    const float4* z4 = reinterpret_cast<const float4*>(g_z);

    float4 s = make_float4(0.f, 0.f, 0.f, 0.f);
    int i = 0;
    for (; i + 4 <= deg; i += 4) {
        int4 nn = *reinterpret_cast<const int4*>(&nb[i]);
        float4 a = z4[(size_t)nn.x * TPT + c];
        float4 b = z4[(size_t)nn.y * TPT + c];
        float4 cc = z4[(size_t)nn.z * TPT + c];
        float4 d = z4[(size_t)nn.w * TPT + c];
        s = f4add(s, f4add(f4add(a, b), f4add(cc, d)));
    }
    for (; i < deg; i++)
        s = f4add(s, z4[(size_t)nb[i] * TPT + c]);

    float dinv = (deg > 0) ? (1.0f / (float)deg) : 0.0f;
    float4 rr = reinterpret_cast<const float4*>(g_r)[(size_t)t * TPT + c];
    float4 o;
    o.x = s.x * dinv + rr.x;
    o.y = s.y * dinv + rr.y;
    o.z = s.z * dinv + rr.z;
    o.w = s.w * dinv + rr.w;
    if (RELU) {
        o.x = fmaxf(o.x, 0.f); o.y = fmaxf(o.y, 0.f);
        o.z = fmaxf(o.z, 0.f); o.w = fmaxf(o.w, 0.f);
    }
    reinterpret_cast<float4*>(out)[(size_t)t * TPT + c] = o;
}

extern "C" void kernel_launch(void* const* d_in, const int* in_sizes, int n_in,
                              void* d_out, int out_size) {
    const float* x   = (const float*)d_in[0];
    const float* adj = (const float*)d_in[1];
    const float* Wl0 = (const float*)d_in[2];
    const float* b0  = (const float*)d_in[3];
    const float* Wr0 = (const float*)d_in[4];
    const float* Wl1 = (const float*)d_in[5];
    const float* b1  = (const float*)d_in[6];
    const float* Wr1 = (const float*)d_in[7];
    const float* Wl2 = (const float*)d_in[8];
    const float* b2  = (const float*)d_in[9];
    const float* Wr2 = (const float*)d_in[10];
    float* out = (float*)d_out;

    zero_cnt_kernel<<<NN / 256, 256>>>();

    // Layer-0 transform (x -> z,r) overlapped with adjacency scan (lean regs).
    fused_gemm0_build_kernel<<<GEMM0_BLOCKS + BUILD_BLOCKS, 256>>>(x, adj, Wl0, Wr0, b0);

    // Layer 0 aggregate+activate: g_h = relu(mean(z) + r)
    gather_kernel<128, true><<<NN / 4, 128>>>(nullptr, 1);

    // Layer 1 (virtual cols = 256 -> 2 col blocks)
    gemm_kernel<<<dim3(NN / 128, 2), 256>>>(Wl1, Wr1, b1, 128);
    gather_kernel<128, true><<<NN / 4, 128>>>(nullptr, 1);

    // Layer 2 (fout = 64, virtual cols = 128 -> 1 col block); final gather -> d_out
    gemm_kernel<<<dim3(NN / 128, 1), 256>>>(Wl2, Wr2, b2, 64);
    gather_kernel<64, false><<<NN / 8, 128>>>(out, 0);
}